// round 6
// baseline (speedup 1.0000x reference)
#include <cuda_runtime.h>
#include <cstdint>
#include <cstddef>

#define N_NODES 50000
#define N_EDGES 800000
#define C_HID   256
#define C_OUT   128
#define N_DROP  (N_NODES * C_HID)         // 12,800,000
#define SCAN_B  512
#define NB      ((N_NODES + SCAN_B - 1) / SCAN_B)   // 98

// ---------------- scratch (static device globals; no allocation) ----------------
__device__ __align__(16) float g_deg [N_NODES];
__device__ __align__(16) float g_dinv[N_NODES];
__device__ __align__(16) int   g_src [N_EDGES];
__device__ __align__(16) int   g_dst [N_EDGES];
__device__ __align__(16) int   g_cnt [N_NODES];
__device__ __align__(16) int   g_rp  [N_NODES + 1];
__device__ __align__(16) int   g_cur [N_NODES];
__device__ __align__(16) int   g_bsum[NB];
__device__ __align__(16) int   g_boff[NB];
__device__ __align__(16) int   g_ss  [N_EDGES];   // CSR: src sorted by dst
__device__ __align__(16) float g_sn  [N_EDGES];   // CSR: norm sorted by dst
__device__ __align__(16) float g_h1  [(size_t)N_NODES * C_HID];
__device__ __align__(16) float g_agg1[(size_t)N_NODES * C_HID];
__device__ __align__(16) float g_h1d [(size_t)N_NODES * C_HID];
__device__ __align__(16) float g_h2  [(size_t)N_NODES * C_OUT];
__device__ int g_mode;      // 0=int64, 1=int32, 2=float32 storage of edge_index
__device__ int g_any_odd;
__device__ int g_any_big;

// ---------------- threefry-2x32 core (JAX-exact rounds/injections) ----------------
__device__ __forceinline__ uint32_t rotl32(uint32_t x, int d) {
    return (x << d) | (x >> (32 - d));
}
__device__ __forceinline__ void threefry2x32(uint32_t k0, uint32_t k1,
                                             uint32_t& x0, uint32_t& x1) {
    uint32_t ks0 = k0, ks1 = k1, ks2 = k0 ^ k1 ^ 0x1BD11BDAu;
    x0 += ks0; x1 += ks1;
#define TF_GROUP(a,b,c,d) \
    x0 += x1; x1 = rotl32(x1,a); x1 ^= x0; \
    x0 += x1; x1 = rotl32(x1,b); x1 ^= x0; \
    x0 += x1; x1 = rotl32(x1,c); x1 ^= x0; \
    x0 += x1; x1 = rotl32(x1,d); x1 ^= x0;
    TF_GROUP(13,15,26,6)   x0 += ks1; x1 += ks2 + 1u;
    TF_GROUP(17,29,16,24)  x0 += ks2; x1 += ks0 + 2u;
    TF_GROUP(13,15,26,6)   x0 += ks0; x1 += ks1 + 3u;
    TF_GROUP(17,29,16,24)  x0 += ks1; x1 += ks2 + 4u;
    TF_GROUP(13,15,26,6)   x0 += ks2; x1 += ks0 + 5u;
#undef TF_GROUP
}

// ---------------- dtype detection ----------------
// Node ids are < 50000 (< 2^16). As int32 words they are < 0x0000C350.
// As float32, any id >= 1.0 has bits >= 0x3F800000. As int64, odd (high) words = 0.
__global__ void k_detect(const unsigned* __restrict__ eiw) {
    int t = threadIdx.x;
    if (t == 0) { g_any_odd = 0; g_any_big = 0; }
    __syncthreads();
    unsigned v0 = eiw[2 * t];
    unsigned v1 = eiw[2 * t + 1];
    if (v0 >= 0x30000000u || v1 >= 0x30000000u) atomicExch(&g_any_big, 1);
    if (v1 != 0u) atomicExch(&g_any_odd, 1);
    __syncthreads();
    if (t == 0) g_mode = g_any_big ? 2 : (g_any_odd ? 1 : 0);
}

__global__ void k_init() {
    int n = blockIdx.x * blockDim.x + threadIdx.x;
    if (n < N_NODES) { g_deg[n] = 1.0f; g_cnt[n] = 0; }
}

__global__ void k_prep_edges(const void* __restrict__ ei_raw,
                             const float* __restrict__ w) {
    int e = blockIdx.x * blockDim.x + threadIdx.x;
    if (e >= N_EDGES) return;
    int s, d;
    int mode = g_mode;
    if (mode == 2) {
        const float* ei = (const float*)ei_raw;
        s = (int)ei[e];
        d = (int)ei[N_EDGES + e];
    } else if (mode == 1) {
        const int* ei = (const int*)ei_raw;
        s = ei[e];
        d = ei[N_EDGES + e];
    } else {
        const long long* ei = (const long long*)ei_raw;
        s = (int)ei[e];
        d = (int)ei[N_EDGES + e];
    }
    s = min(max(s, 0), N_NODES - 1);
    d = min(max(d, 0), N_NODES - 1);
    g_src[e] = s; g_dst[e] = d;
    atomicAdd(&g_deg[d], w[e]);
    atomicAdd(&g_cnt[d], 1);
}

__global__ void k_dinv() {
    int n = blockIdx.x * blockDim.x + threadIdx.x;
    if (n < N_NODES) g_dinv[n] = rsqrtf(g_deg[n]);   // deg >= 1 always
}

// ---------------- 3-kernel exclusive scan of g_cnt -> g_rp ----------------
__global__ void __launch_bounds__(SCAN_B) k_scan1() {
    __shared__ int ws[16];
    int b = blockIdx.x;
    int t = threadIdx.x;
    int i = b * SCAN_B + t;
    int lane = t & 31, wid = t >> 5;
    int v = (i < N_NODES) ? g_cnt[i] : 0;
    int x = v;
#pragma unroll
    for (int o = 1; o < 32; o <<= 1) {
        int y = __shfl_up_sync(~0u, x, o);
        if (lane >= o) x += y;
    }
    if (lane == 31) ws[wid] = x;
    __syncthreads();
    if (wid == 0) {
        int s = (lane < 16) ? ws[lane] : 0;
#pragma unroll
        for (int o = 1; o < 16; o <<= 1) {
            int y = __shfl_up_sync(~0u, s, o);
            if (lane >= o) s += y;
        }
        if (lane < 16) ws[lane] = s;
    }
    __syncthreads();
    int excl = x - v + (wid > 0 ? ws[wid - 1] : 0);
    if (i < N_NODES) g_rp[i] = excl;
    if (t == 0) g_bsum[b] = ws[15];
}

__global__ void k_scan2() {   // one block of 128 threads
    __shared__ int ws[4];
    int t = threadIdx.x;
    int lane = t & 31, wid = t >> 5;
    int v = (t < NB) ? g_bsum[t] : 0;
    int x = v;
#pragma unroll
    for (int o = 1; o < 32; o <<= 1) {
        int y = __shfl_up_sync(~0u, x, o);
        if (lane >= o) x += y;
    }
    if (lane == 31) ws[wid] = x;
    __syncthreads();
    if (wid == 0 && lane < 4) {
        int s = ws[lane];
#pragma unroll
        for (int o = 1; o < 4; o <<= 1) {
            int y = __shfl_up_sync(0xFu, s, o);
            if (lane >= o) s += y;
        }
        ws[lane] = s;
    }
    __syncthreads();
    int excl = x - v + (wid > 0 ? ws[wid - 1] : 0);
    if (t < NB) g_boff[t] = excl;
}

__global__ void __launch_bounds__(SCAN_B) k_scan3() {
    int b = blockIdx.x;
    int i = b * SCAN_B + threadIdx.x;
    if (i < N_NODES) {
        int r = g_rp[i] + g_boff[b];
        g_rp[i] = r;
        g_cur[i] = r;
    }
    if (i == 0) g_rp[N_NODES] = N_EDGES;
}

// norm + scatter into CSR order
__global__ void k_norm_scatter(const float* __restrict__ w) {
    int e = blockIdx.x * blockDim.x + threadIdx.x;
    if (e >= N_EDGES) return;
    int s = g_src[e], d = g_dst[e];
    float nm = g_dinv[s] * w[e] * g_dinv[d];
    int pos = atomicAdd(&g_cur[d], 1);
    if (pos < N_EDGES) {
        g_ss[pos] = s;
        g_sn[pos] = nm;
    }
}

// ---------------- SGEMM: C[M,Nn] = A[M,K] @ B[K,Nn], all row-major ----------------
__global__ void __launch_bounds__(256) k_sgemm(const float* __restrict__ A,
                                               const float* __restrict__ B,
                                               float* __restrict__ C,
                                               int M, int Nn, int K) {
    __shared__ float As[8][128];
    __shared__ float Bs[8][128];
    const int tid  = threadIdx.x;
    const int brow = blockIdx.y * 128;
    const int bcol = blockIdx.x * 128;
    const int ty = tid >> 4, tx = tid & 15;
    const int arow = tid >> 1;
    const int acol = (tid & 1) * 4;
    const int brl  = tid >> 5;
    const int bcl  = (tid & 31) * 4;

    float acc[8][8];
#pragma unroll
    for (int i = 0; i < 8; i++)
#pragma unroll
        for (int j = 0; j < 8; j++) acc[i][j] = 0.0f;

    const int ar_g = brow + arow;
    const bool a_ok = ar_g < M;

    for (int k0 = 0; k0 < K; k0 += 8) {
        float4 av = make_float4(0.f, 0.f, 0.f, 0.f);
        if (a_ok) av = *(const float4*)&A[(size_t)ar_g * K + k0 + acol];
        As[acol + 0][arow] = av.x;
        As[acol + 1][arow] = av.y;
        As[acol + 2][arow] = av.z;
        As[acol + 3][arow] = av.w;
        float4 bv = *(const float4*)&B[(size_t)(k0 + brl) * Nn + bcol + bcl];
        *(float4*)&Bs[brl][bcl] = bv;
        __syncthreads();
#pragma unroll
        for (int k = 0; k < 8; k++) {
            float ar[8], br[8];
            *(float4*)&ar[0] = *(const float4*)&As[k][ty * 8];
            *(float4*)&ar[4] = *(const float4*)&As[k][ty * 8 + 4];
            *(float4*)&br[0] = *(const float4*)&Bs[k][tx * 8];
            *(float4*)&br[4] = *(const float4*)&Bs[k][tx * 8 + 4];
#pragma unroll
            for (int i = 0; i < 8; i++)
#pragma unroll
                for (int j = 0; j < 8; j++)
                    acc[i][j] += ar[i] * br[j];
        }
        __syncthreads();
    }

#pragma unroll
    for (int i = 0; i < 8; i++) {
        int r = brow + ty * 8 + i;
        if (r < M) {
            float4 v0 = make_float4(acc[i][0], acc[i][1], acc[i][2], acc[i][3]);
            float4 v1 = make_float4(acc[i][4], acc[i][5], acc[i][6], acc[i][7]);
            *(float4*)&C[(size_t)r * Nn + bcol + tx * 8]     = v0;
            *(float4*)&C[(size_t)r * Nn + bcol + tx * 8 + 4] = v1;
        }
    }
}

// ---------------- CSR gather aggregation: one warp per node ----------------
// out[n] = bias + dinv[n]^2 * h[n] + sum_{j in row n} norm[j] * h[src[j]]
template <int C>
__global__ void __launch_bounds__(256) k_agg(const float* __restrict__ h,
                                             const float* __restrict__ bias,
                                             float* __restrict__ out) {
    const int warp = (blockIdx.x * blockDim.x + threadIdx.x) >> 5;
    const int lane = threadIdx.x & 31;
    if (warp >= N_NODES) return;
    constexpr int V = C / 128;            // float4 chunks per lane
    const float4* h4 = (const float4*)h;
    const float4* b4 = (const float4*)bias;
    float di = g_dinv[warp];
    float sw = di * di;

    float4 acc[V];
#pragma unroll
    for (int v = 0; v < V; v++) {
        float4 hv = h4[(size_t)warp * (C / 4) + v * 32 + lane];
        float4 bv = b4[v * 32 + lane];
        acc[v] = make_float4(bv.x + sw * hv.x, bv.y + sw * hv.y,
                             bv.z + sw * hv.z, bv.w + sw * hv.w);
    }

    int beg = g_rp[warp], end = g_rp[warp + 1];
    for (int j = beg; j < end; j++) {
        int s = g_ss[j];
        float nm = g_sn[j];
#pragma unroll
        for (int v = 0; v < V; v++) {
            float4 t = h4[(size_t)s * (C / 4) + v * 32 + lane];
            acc[v].x += nm * t.x;
            acc[v].y += nm * t.y;
            acc[v].z += nm * t.z;
            acc[v].w += nm * t.w;
        }
    }

    float4* o4 = (float4*)out;
#pragma unroll
    for (int v = 0; v < V; v++)
        o4[(size_t)warp * (C / 4) + v * 32 + lane] = acc[v];
}

// ---------------- relu + dropout, JAX partitionable-threefry convention ----------------
// jax_threefry_partitionable=True (modern default): element i of the flat array uses
// the 64-bit counter i split as (hi=0, lo=i); 32-bit output = y0 ^ y1.
__global__ void k_relu_dropout(const float* __restrict__ agg, float* __restrict__ out) {
    int i = blockIdx.x * blockDim.x + threadIdx.x;
    if (i >= N_DROP) return;
    uint32_t x0 = 0u, x1 = (uint32_t)i;
    threefry2x32(0u, 42u, x0, x1);
    uint32_t bits = x0 ^ x1;
    float u = __uint_as_float((bits >> 9) | 0x3f800000u) - 1.0f;
    float v = fmaxf(agg[i], 0.0f);
    out[i] = (u < 0.5f) ? 2.0f * v : 0.0f;
}

// ---------------- launch ----------------
extern "C" void kernel_launch(void* const* d_in, const int* in_sizes, int n_in,
                              void* d_out, int out_size) {
    // Identify inputs by element count (robust to metadata ordering):
    //   x: 6,400,000  edge_index: 1,600,000  weight: 800,000
    //   W1/W2: 32,768 (first seen = W1)  b1: 256  b2: 128
    const float* x = nullptr; const void* ei = nullptr; const float* w = nullptr;
    const float* W1 = nullptr; const float* b1 = nullptr;
    const float* W2 = nullptr; const float* b2 = nullptr;
    for (int i = 0; i < n_in; i++) {
        int sz = in_sizes[i];
        const void* p = d_in[i];
        switch (sz) {
            case 6400000: x  = (const float*)p; break;
            case 1600000: ei = p; break;
            case 800000:  w  = (const float*)p; break;
            case 32768:   if (!W1) W1 = (const float*)p; else W2 = (const float*)p; break;
            case 256:     b1 = (const float*)p; break;
            case 128:     b2 = (const float*)p; break;
            default: break;
        }
    }
    float* out = (float*)d_out;

    float* h1;   cudaGetSymbolAddress((void**)&h1,   g_h1);
    float* agg1; cudaGetSymbolAddress((void**)&agg1, g_agg1);
    float* h1d;  cudaGetSymbolAddress((void**)&h1d,  g_h1d);
    float* h2;   cudaGetSymbolAddress((void**)&h2,   g_h2);

    const int TB = 256;
    // dtype detect + graph prep + CSR build
    k_detect<<<1, 512>>>((const unsigned*)ei);
    k_init<<<(N_NODES + TB - 1) / TB, TB>>>();
    k_prep_edges<<<(N_EDGES + TB - 1) / TB, TB>>>(ei, w);
    k_dinv<<<(N_NODES + TB - 1) / TB, TB>>>();
    k_scan1<<<NB, SCAN_B>>>();
    k_scan2<<<1, 128>>>();
    k_scan3<<<NB, SCAN_B>>>();
    k_norm_scatter<<<(N_EDGES + TB - 1) / TB, TB>>>(w);

    // Layer 1
    k_sgemm<<<dim3(C_HID / 128, (N_NODES + 127) / 128), 256>>>(x, W1, h1, N_NODES, C_HID, 128);
    k_agg<C_HID><<<(N_NODES * 32 + TB - 1) / TB, TB>>>(h1, b1, agg1);
    k_relu_dropout<<<(N_DROP + TB - 1) / TB, TB>>>(agg1, h1d);

    // Layer 2
    k_sgemm<<<dim3(C_OUT / 128, (N_NODES + 127) / 128), 256>>>(h1d, W2, h2, N_NODES, C_OUT, C_HID);
    k_agg<C_OUT><<<(N_NODES * 32 + TB - 1) / TB, TB>>>(h2, b2, out);
}

// round 7
// speedup vs baseline: 1.7578x; 1.7578x over previous
#include <cuda_runtime.h>
#include <cstdint>
#include <cstddef>

#define N_NODES 50000
#define N_PAD   50048                      // padded row count (multiple of 128)
#define N_EDGES 800000
#define C_HID   256
#define C_OUT   128
#define SCAN_B  512
#define NB      ((N_NODES + SCAN_B - 1) / SCAN_B)   // 98

// ---------------- scratch (static device globals; no allocation) ----------------
__device__ __align__(16) float g_deg [N_NODES];
__device__ __align__(16) float g_dinv[N_NODES];
__device__ __align__(16) int   g_src [N_EDGES];
__device__ __align__(16) int   g_dst [N_EDGES];
__device__ __align__(16) int   g_cnt [N_NODES];
__device__ __align__(16) int   g_rp  [N_NODES + 1];
__device__ __align__(16) int   g_cur [N_NODES];
__device__ __align__(16) int   g_bsum[NB];
__device__ __align__(16) int   g_boff[NB];
__device__ __align__(16) int   g_ss  [N_EDGES];   // CSR: src sorted by dst
__device__ __align__(16) float g_sn  [N_EDGES];   // CSR: norm sorted by dst
__device__ __align__(16) float g_ax  [(size_t)N_PAD * C_OUT];   // A_hat @ x   [N,128]
__device__ __align__(16) float g_h1d [(size_t)N_PAD * C_HID];   // relu+drop((ax)W1+b1)
__device__ __align__(16) float g_h2  [(size_t)N_PAD * C_OUT];   // h1d @ W2
__device__ int g_mode;      // 0=int64, 1=int32, 2=float32 storage of edge_index
__device__ int g_any_odd;
__device__ int g_any_big;

// ---------------- threefry-2x32 (JAX partitionable convention) ----------------
__device__ __forceinline__ uint32_t rotl32(uint32_t x, int d) {
    return (x << d) | (x >> (32 - d));
}
__device__ __forceinline__ void threefry2x32(uint32_t k0, uint32_t k1,
                                             uint32_t& x0, uint32_t& x1) {
    uint32_t ks0 = k0, ks1 = k1, ks2 = k0 ^ k1 ^ 0x1BD11BDAu;
    x0 += ks0; x1 += ks1;
#define TF_GROUP(a,b,c,d) \
    x0 += x1; x1 = rotl32(x1,a); x1 ^= x0; \
    x0 += x1; x1 = rotl32(x1,b); x1 ^= x0; \
    x0 += x1; x1 = rotl32(x1,c); x1 ^= x0; \
    x0 += x1; x1 = rotl32(x1,d); x1 ^= x0;
    TF_GROUP(13,15,26,6)   x0 += ks1; x1 += ks2 + 1u;
    TF_GROUP(17,29,16,24)  x0 += ks2; x1 += ks0 + 2u;
    TF_GROUP(13,15,26,6)   x0 += ks0; x1 += ks1 + 3u;
    TF_GROUP(17,29,16,24)  x0 += ks1; x1 += ks2 + 4u;
    TF_GROUP(13,15,26,6)   x0 += ks2; x1 += ks0 + 5u;
#undef TF_GROUP
}
// keep-decision for flat element i of the (50000,256) dropout array, key (0,42)
__device__ __forceinline__ bool drop_keep(uint32_t i) {
    uint32_t x0 = 0u, x1 = i;
    threefry2x32(0u, 42u, x0, x1);
    uint32_t bits = x0 ^ x1;
    float u = __uint_as_float((bits >> 9) | 0x3f800000u) - 1.0f;
    return u < 0.5f;
}

__device__ __forceinline__ uint32_t f2tf32(float f) {
    uint32_t r;
    asm("cvt.rna.tf32.f32 %0, %1;" : "=r"(r) : "f"(f));
    return r;
}

// ---------------- dtype detection ----------------
__global__ void k_detect(const unsigned* __restrict__ eiw) {
    int t = threadIdx.x;
    if (t == 0) { g_any_odd = 0; g_any_big = 0; }
    __syncthreads();
    unsigned v0 = eiw[2 * t];
    unsigned v1 = eiw[2 * t + 1];
    if (v0 >= 0x30000000u || v1 >= 0x30000000u) atomicExch(&g_any_big, 1);
    if (v1 != 0u) atomicExch(&g_any_odd, 1);
    __syncthreads();
    if (t == 0) g_mode = g_any_big ? 2 : (g_any_odd ? 1 : 0);
}

__global__ void k_init() {
    int n = blockIdx.x * blockDim.x + threadIdx.x;
    if (n < N_NODES) { g_deg[n] = 1.0f; g_cnt[n] = 0; }
}

__global__ void k_prep_edges(const void* __restrict__ ei_raw,
                             const float* __restrict__ w) {
    int e = blockIdx.x * blockDim.x + threadIdx.x;
    if (e >= N_EDGES) return;
    int s, d;
    int mode = g_mode;
    if (mode == 2) {
        const float* ei = (const float*)ei_raw;
        s = (int)ei[e];
        d = (int)ei[N_EDGES + e];
    } else if (mode == 1) {
        const int* ei = (const int*)ei_raw;
        s = ei[e];
        d = ei[N_EDGES + e];
    } else {
        const long long* ei = (const long long*)ei_raw;
        s = (int)ei[e];
        d = (int)ei[N_EDGES + e];
    }
    s = min(max(s, 0), N_NODES - 1);
    d = min(max(d, 0), N_NODES - 1);
    g_src[e] = s; g_dst[e] = d;
    atomicAdd(&g_deg[d], w[e]);
    atomicAdd(&g_cnt[d], 1);
}

__global__ void k_dinv() {
    int n = blockIdx.x * blockDim.x + threadIdx.x;
    if (n < N_NODES) g_dinv[n] = rsqrtf(g_deg[n]);
}

// ---------------- 3-kernel exclusive scan of g_cnt -> g_rp ----------------
__global__ void __launch_bounds__(SCAN_B) k_scan1() {
    __shared__ int ws[16];
    int b = blockIdx.x, t = threadIdx.x;
    int i = b * SCAN_B + t;
    int lane = t & 31, wid = t >> 5;
    int v = (i < N_NODES) ? g_cnt[i] : 0;
    int x = v;
#pragma unroll
    for (int o = 1; o < 32; o <<= 1) {
        int y = __shfl_up_sync(~0u, x, o);
        if (lane >= o) x += y;
    }
    if (lane == 31) ws[wid] = x;
    __syncthreads();
    if (wid == 0) {
        int s = (lane < 16) ? ws[lane] : 0;
#pragma unroll
        for (int o = 1; o < 16; o <<= 1) {
            int y = __shfl_up_sync(~0u, s, o);
            if (lane >= o) s += y;
        }
        if (lane < 16) ws[lane] = s;
    }
    __syncthreads();
    int excl = x - v + (wid > 0 ? ws[wid - 1] : 0);
    if (i < N_NODES) g_rp[i] = excl;
    if (t == 0) g_bsum[b] = ws[15];
}

__global__ void k_scan2() {
    __shared__ int ws[4];
    int t = threadIdx.x;
    int lane = t & 31, wid = t >> 5;
    int v = (t < NB) ? g_bsum[t] : 0;
    int x = v;
#pragma unroll
    for (int o = 1; o < 32; o <<= 1) {
        int y = __shfl_up_sync(~0u, x, o);
        if (lane >= o) x += y;
    }
    if (lane == 31) ws[wid] = x;
    __syncthreads();
    if (wid == 0 && lane < 4) {
        int s = ws[lane];
#pragma unroll
        for (int o = 1; o < 4; o <<= 1) {
            int y = __shfl_up_sync(0xFu, s, o);
            if (lane >= o) s += y;
        }
        ws[lane] = s;
    }
    __syncthreads();
    int excl = x - v + (wid > 0 ? ws[wid - 1] : 0);
    if (t < NB) g_boff[t] = excl;
}

__global__ void __launch_bounds__(SCAN_B) k_scan3() {
    int b = blockIdx.x;
    int i = b * SCAN_B + threadIdx.x;
    if (i < N_NODES) {
        int r = g_rp[i] + g_boff[b];
        g_rp[i] = r;
        g_cur[i] = r;
    }
    if (i == 0) g_rp[N_NODES] = N_EDGES;
}

__global__ void k_norm_scatter(const float* __restrict__ w) {
    int e = blockIdx.x * blockDim.x + threadIdx.x;
    if (e >= N_EDGES) return;
    int s = g_src[e], d = g_dst[e];
    float nm = g_dinv[s] * w[e] * g_dinv[d];
    int pos = atomicAdd(&g_cur[d], 1);
    if (pos < N_EDGES) {
        g_ss[pos] = s;
        g_sn[pos] = nm;
    }
}

// ---------------- CSR gather aggregation (C=128): one warp per node ----------------
// out[n] = (BIAS? bias : 0) + dinv[n]^2 * h[n] + sum_{j in row n} norm[j]*h[src[j]]
template <bool BIAS>
__global__ void __launch_bounds__(256) k_agg128(const float* __restrict__ h,
                                                const float* __restrict__ bias,
                                                float* __restrict__ out) {
    const int warp = (blockIdx.x * blockDim.x + threadIdx.x) >> 5;
    const int lane = threadIdx.x & 31;
    if (warp >= N_NODES) return;
    const float4* h4 = (const float4*)h;
    float di = g_dinv[warp];
    float sw = di * di;

    float4 hv = h4[(size_t)warp * 32 + lane];
    float4 acc = make_float4(sw * hv.x, sw * hv.y, sw * hv.z, sw * hv.w);
    if (BIAS) {
        float4 bv = ((const float4*)bias)[lane];
        acc.x += bv.x; acc.y += bv.y; acc.z += bv.z; acc.w += bv.w;
    }

    int beg = g_rp[warp], end = g_rp[warp + 1];
    for (int j = beg; j < end; j++) {
        int s = g_ss[j];
        float nm = g_sn[j];
        float4 t = h4[(size_t)s * 32 + lane];
        acc.x += nm * t.x;
        acc.y += nm * t.y;
        acc.z += nm * t.z;
        acc.w += nm * t.w;
    }
    ((float4*)out)[(size_t)warp * 32 + lane] = acc;
}

// ---------------- tf32 tensor-core GEMM: C[M,Nn] = A[M,K] @ B[K,Nn] ----------------
// BM=128, BN=128, BK=8. 256 threads = 8 warps (4 m-slices x 2 n-slices, 32x64/warp).
// RELU_DROP epilogue: C = dropout(relu(acc + bias[col])) with JAX mask on flat idx.
template <bool RELU_DROP>
__global__ void __launch_bounds__(256) k_gemm_tc(const float* __restrict__ A,
                                                 const float* __restrict__ B,
                                                 const float* __restrict__ bias,
                                                 float* __restrict__ C,
                                                 int M, int Nn, int K) {
    __shared__ uint32_t As[128][12];   // [m][k], stride 12: conflict-free frags
    __shared__ uint32_t Bs[8][136];    // [k][n], stride 136: conflict-free frags
    const int tid  = threadIdx.x;
    const int brow = blockIdx.y * 128;
    const int bcol = blockIdx.x * 128;
    const int warp = tid >> 5, lane = tid & 31;
    const int wm = warp & 3, wn = warp >> 1 & 2 ? 1 : (warp >> 2); // warp>>2 in {0,1}
    const int g  = lane >> 2, tg = lane & 3;

    float acc[2][8][4];
#pragma unroll
    for (int mt = 0; mt < 2; mt++)
#pragma unroll
        for (int nt = 0; nt < 8; nt++)
#pragma unroll
            for (int r = 0; r < 4; r++) acc[mt][nt][r] = 0.0f;

    const int arow = tid >> 1;            // 0..127
    const int acol = (tid & 1) * 4;       // 0 or 4
    const int bk   = tid >> 5;            // 0..7
    const int bcl  = (tid & 31) * 4;      // 0..124
    const int ar_g = brow + arow;
    const bool a_ok = ar_g < M;

    // prefetch iter 0
    float4 av = make_float4(0.f, 0.f, 0.f, 0.f);
    if (a_ok) av = *(const float4*)&A[(size_t)ar_g * K + acol];
    float4 bv = *(const float4*)&B[(size_t)bk * Nn + bcol + bcl];

    const int n_iter = K >> 3;
    for (int it = 0; it < n_iter; it++) {
        // stage current tile to smem (tf32-converted)
        uint4 at = make_uint4(f2tf32(av.x), f2tf32(av.y), f2tf32(av.z), f2tf32(av.w));
        uint4 bt = make_uint4(f2tf32(bv.x), f2tf32(bv.y), f2tf32(bv.z), f2tf32(bv.w));
        *(uint4*)&As[arow][acol] = at;
        *(uint4*)&Bs[bk][bcl]    = bt;
        __syncthreads();
        // prefetch next
        if (it + 1 < n_iter) {
            int k0 = (it + 1) << 3;
            av = make_float4(0.f, 0.f, 0.f, 0.f);
            if (a_ok) av = *(const float4*)&A[(size_t)ar_g * K + k0 + acol];
            bv = *(const float4*)&B[(size_t)(k0 + bk) * Nn + bcol + bcl];
        }
        // fragments + mma
        uint32_t af[2][4];
#pragma unroll
        for (int mt = 0; mt < 2; mt++) {
            int rb = wm * 32 + mt * 16;
            af[mt][0] = As[rb + g][tg];
            af[mt][1] = As[rb + g + 8][tg];
            af[mt][2] = As[rb + g][tg + 4];
            af[mt][3] = As[rb + g + 8][tg + 4];
        }
#pragma unroll
        for (int nt = 0; nt < 8; nt++) {
            int cb = wn * 64 + nt * 8 + g;
            uint32_t b0 = Bs[tg][cb];
            uint32_t b1 = Bs[tg + 4][cb];
#pragma unroll
            for (int mt = 0; mt < 2; mt++) {
                asm volatile(
                    "mma.sync.aligned.m16n8k8.row.col.f32.tf32.tf32.f32 "
                    "{%0,%1,%2,%3}, {%4,%5,%6,%7}, {%8,%9}, {%0,%1,%2,%3};\n"
                    : "+f"(acc[mt][nt][0]), "+f"(acc[mt][nt][1]),
                      "+f"(acc[mt][nt][2]), "+f"(acc[mt][nt][3])
                    : "r"(af[mt][0]), "r"(af[mt][1]), "r"(af[mt][2]), "r"(af[mt][3]),
                      "r"(b0), "r"(b1));
            }
        }
        __syncthreads();
    }

    // epilogue
#pragma unroll
    for (int mt = 0; mt < 2; mt++) {
#pragma unroll
        for (int half = 0; half < 2; half++) {
            int row = brow + wm * 32 + mt * 16 + g + half * 8;
            if (row >= M) continue;
#pragma unroll
            for (int nt = 0; nt < 8; nt++) {
                int col = bcol + wn * 64 + nt * 8 + tg * 2;
                float v0 = acc[mt][nt][half * 2 + 0];
                float v1 = acc[mt][nt][half * 2 + 1];
                if (RELU_DROP) {
                    v0 = fmaxf(v0 + __ldg(&bias[col]), 0.0f);
                    v1 = fmaxf(v1 + __ldg(&bias[col + 1]), 0.0f);
                    uint32_t i0 = (uint32_t)row * 256u + (uint32_t)col;
                    v0 = drop_keep(i0)      ? 2.0f * v0 : 0.0f;
                    v1 = drop_keep(i0 + 1u) ? 2.0f * v1 : 0.0f;
                }
                *(float2*)&C[(size_t)row * Nn + col] = make_float2(v0, v1);
            }
        }
    }
}

// ---------------- launch ----------------
extern "C" void kernel_launch(void* const* d_in, const int* in_sizes, int n_in,
                              void* d_out, int out_size) {
    // Identify inputs by element count (robust to metadata ordering)
    const float* x = nullptr; const void* ei = nullptr; const float* w = nullptr;
    const float* W1 = nullptr; const float* b1 = nullptr;
    const float* W2 = nullptr; const float* b2 = nullptr;
    for (int i = 0; i < n_in; i++) {
        int sz = in_sizes[i];
        const void* p = d_in[i];
        switch (sz) {
            case 6400000: x  = (const float*)p; break;
            case 1600000: ei = p; break;
            case 800000:  w  = (const float*)p; break;
            case 32768:   if (!W1) W1 = (const float*)p; else W2 = (const float*)p; break;
            case 256:     b1 = (const float*)p; break;
            case 128:     b2 = (const float*)p; break;
            default: break;
        }
    }
    float* out = (float*)d_out;

    float* ax;  cudaGetSymbolAddress((void**)&ax,  g_ax);
    float* h1d; cudaGetSymbolAddress((void**)&h1d, g_h1d);
    float* h2;  cudaGetSymbolAddress((void**)&h2,  g_h2);

    const int TB = 256;
    // dtype detect + graph prep + CSR build
    k_detect<<<1, 512>>>((const unsigned*)ei);
    k_init<<<(N_NODES + TB - 1) / TB, TB>>>();
    k_prep_edges<<<(N_EDGES + TB - 1) / TB, TB>>>(ei, w);
    k_dinv<<<(N_NODES + TB - 1) / TB, TB>>>();
    k_scan1<<<NB, SCAN_B>>>();
    k_scan2<<<1, 128>>>();
    k_scan3<<<NB, SCAN_B>>>();
    k_norm_scatter<<<(N_EDGES + TB - 1) / TB, TB>>>(w);

    // Layer 1 (reordered): ax = A_hat @ x ; h1d = dropout(relu(ax@W1 + b1))
    k_agg128<false><<<(N_NODES * 32 + TB - 1) / TB, TB>>>(x, nullptr, ax);
    k_gemm_tc<true><<<dim3(C_HID / 128, (N_NODES + 127) / 128), 256>>>(
        ax, W1, b1, h1d, N_NODES, C_HID, 128);

    // Layer 2: h2 = h1d @ W2 ; out = A_hat @ h2 + b2
    k_gemm_tc<false><<<dim3(C_OUT / 128, (N_NODES + 127) / 128), 256>>>(
        h1d, W2, nullptr, h2, N_NODES, C_OUT, C_HID);
    k_agg128<true><<<(N_NODES * 32 + TB - 1) / TB, TB>>>(h2, b2, out);
}

// round 8
// speedup vs baseline: 1.7826x; 1.0141x over previous
#include <cuda_runtime.h>
#include <cuda_fp16.h>
#include <cstdint>
#include <cstddef>

#define N_NODES 50000
#define N_PAD   50048                      // padded row count (multiple of 128)
#define N_EDGES 800000
#define C_HID   256
#define C_OUT   128
#define SCAN_B  512
#define NB      ((N_NODES + SCAN_B - 1) / SCAN_B)   // 98

// ---------------- scratch (static device globals; no allocation) ----------------
__device__ __align__(16) float  g_deg [N_NODES];
__device__ __align__(16) float  g_dinv[N_NODES];
__device__ __align__(16) int    g_src [N_EDGES];
__device__ __align__(16) int    g_dst [N_EDGES];
__device__ __align__(16) int    g_cnt [N_NODES];
__device__ __align__(16) int    g_rp  [N_NODES + 1];
__device__ __align__(16) int    g_cur [N_NODES];
__device__ __align__(16) int    g_bsum[NB];
__device__ __align__(16) int    g_boff[NB];
__device__ __align__(16) int    g_ss  [N_EDGES];   // CSR: src sorted by dst
__device__ __align__(16) float  g_sn  [N_EDGES];   // CSR: norm sorted by dst
__device__ __align__(16) __half g_xh  [(size_t)N_NODES * C_OUT];   // x in fp16
__device__ __align__(16) float  g_ax  [(size_t)N_PAD * C_OUT];     // A_hat @ x
__device__ __align__(16) float  g_h1d [(size_t)N_PAD * C_HID];     // relu+drop(axW1+b1)
__device__ __align__(16) __half g_h2h [(size_t)N_PAD * C_OUT];     // h1d @ W2 in fp16
__device__ int g_mode;      // 0=int64, 1=int32, 2=float32 storage of edge_index

// ---------------- threefry-2x32 (JAX partitionable convention) ----------------
__device__ __forceinline__ uint32_t rotl32(uint32_t x, int d) {
    return (x << d) | (x >> (32 - d));
}
__device__ __forceinline__ void threefry2x32(uint32_t k0, uint32_t k1,
                                             uint32_t& x0, uint32_t& x1) {
    uint32_t ks0 = k0, ks1 = k1, ks2 = k0 ^ k1 ^ 0x1BD11BDAu;
    x0 += ks0; x1 += ks1;
#define TF_GROUP(a,b,c,d) \
    x0 += x1; x1 = rotl32(x1,a); x1 ^= x0; \
    x0 += x1; x1 = rotl32(x1,b); x1 ^= x0; \
    x0 += x1; x1 = rotl32(x1,c); x1 ^= x0; \
    x0 += x1; x1 = rotl32(x1,d); x1 ^= x0;
    TF_GROUP(13,15,26,6)   x0 += ks1; x1 += ks2 + 1u;
    TF_GROUP(17,29,16,24)  x0 += ks2; x1 += ks0 + 2u;
    TF_GROUP(13,15,26,6)   x0 += ks0; x1 += ks1 + 3u;
    TF_GROUP(17,29,16,24)  x0 += ks1; x1 += ks2 + 4u;
    TF_GROUP(13,15,26,6)   x0 += ks2; x1 += ks0 + 5u;
#undef TF_GROUP
}
// keep ⟺ u<0.5 ⟺ ((y0^y1)>>9)/2^23 < 0.5 ⟺ (y0^y1) < 2^31 (sign-bit test)
__device__ __forceinline__ bool drop_keep(uint32_t i) {
    uint32_t x0 = 0u, x1 = i;
    threefry2x32(0u, 42u, x0, x1);
    return ((x0 ^ x1) & 0x80000000u) == 0u;
}

__device__ __forceinline__ uint32_t f2tf32(float f) {
    uint32_t r;
    asm("cvt.rna.tf32.f32 %0, %1;" : "=r"(r) : "f"(f));
    return r;
}

// ---------------- init + dtype detection (fused) ----------------
__global__ void k_init(const unsigned* __restrict__ eiw) {
    int n = blockIdx.x * blockDim.x + threadIdx.x;
    if (n < N_NODES) { g_deg[n] = 1.0f; g_cnt[n] = 0; }
    if (blockIdx.x == 0) {
        __shared__ int s_odd, s_big;
        int t = threadIdx.x;
        if (t == 0) { s_odd = 0; s_big = 0; }
        __syncthreads();
        unsigned v0 = eiw[2 * t];
        unsigned v1 = eiw[2 * t + 1];
        if (v0 >= 0x30000000u || v1 >= 0x30000000u) atomicOr(&s_big, 1);
        if (v1 != 0u) atomicOr(&s_odd, 1);
        __syncthreads();
        if (t == 0) g_mode = s_big ? 2 : (s_odd ? 1 : 0);
    }
}

// ---------------- x -> fp16 ----------------
__global__ void k_cvt_x(const float* __restrict__ x) {
    int i = blockIdx.x * blockDim.x + threadIdx.x;     // float4 index
    if (i >= N_NODES * (C_OUT / 4)) return;
    float4 v = ((const float4*)x)[i];
    __half2 a = __floats2half2_rn(v.x, v.y);
    __half2 b = __floats2half2_rn(v.z, v.w);
    ((uint2*)g_xh)[i] = make_uint2(*(uint32_t*)&a, *(uint32_t*)&b);
}

__global__ void k_prep_edges(const void* __restrict__ ei_raw,
                             const float* __restrict__ w) {
    int e = blockIdx.x * blockDim.x + threadIdx.x;
    if (e >= N_EDGES) return;
    int s, d;
    int mode = g_mode;
    if (mode == 2) {
        const float* ei = (const float*)ei_raw;
        s = (int)ei[e];
        d = (int)ei[N_EDGES + e];
    } else if (mode == 1) {
        const int* ei = (const int*)ei_raw;
        s = ei[e];
        d = ei[N_EDGES + e];
    } else {
        const long long* ei = (const long long*)ei_raw;
        s = (int)ei[e];
        d = (int)ei[N_EDGES + e];
    }
    s = min(max(s, 0), N_NODES - 1);
    d = min(max(d, 0), N_NODES - 1);
    g_src[e] = s; g_dst[e] = d;
    atomicAdd(&g_deg[d], w[e]);
    atomicAdd(&g_cnt[d], 1);
}

// ---------------- scan1 (+ dinv fused) ----------------
__global__ void __launch_bounds__(SCAN_B) k_scan1() {
    __shared__ int ws[16];
    int b = blockIdx.x, t = threadIdx.x;
    int i = b * SCAN_B + t;
    int lane = t & 31, wid = t >> 5;
    int v = (i < N_NODES) ? g_cnt[i] : 0;
    if (i < N_NODES) g_dinv[i] = rsqrtf(g_deg[i]);   // deg >= 1 always
    int x = v;
#pragma unroll
    for (int o = 1; o < 32; o <<= 1) {
        int y = __shfl_up_sync(~0u, x, o);
        if (lane >= o) x += y;
    }
    if (lane == 31) ws[wid] = x;
    __syncthreads();
    if (wid == 0) {
        int s = (lane < 16) ? ws[lane] : 0;
#pragma unroll
        for (int o = 1; o < 16; o <<= 1) {
            int y = __shfl_up_sync(~0u, s, o);
            if (lane >= o) s += y;
        }
        if (lane < 16) ws[lane] = s;
    }
    __syncthreads();
    int excl = x - v + (wid > 0 ? ws[wid - 1] : 0);
    if (i < N_NODES) g_rp[i] = excl;
    if (t == 0) g_bsum[b] = ws[15];
}

__global__ void k_scan2() {
    __shared__ int ws[4];
    int t = threadIdx.x;
    int lane = t & 31, wid = t >> 5;
    int v = (t < NB) ? g_bsum[t] : 0;
    int x = v;
#pragma unroll
    for (int o = 1; o < 32; o <<= 1) {
        int y = __shfl_up_sync(~0u, x, o);
        if (lane >= o) x += y;
    }
    if (lane == 31) ws[wid] = x;
    __syncthreads();
    if (wid == 0 && lane < 4) {
        int s = ws[lane];
#pragma unroll
        for (int o = 1; o < 4; o <<= 1) {
            int y = __shfl_up_sync(0xFu, s, o);
            if (lane >= o) s += y;
        }
        ws[lane] = s;
    }
    __syncthreads();
    int excl = x - v + (wid > 0 ? ws[wid - 1] : 0);
    if (t < NB) g_boff[t] = excl;
}

__global__ void __launch_bounds__(SCAN_B) k_scan3() {
    int b = blockIdx.x;
    int i = b * SCAN_B + threadIdx.x;
    if (i < N_NODES) {
        int r = g_rp[i] + g_boff[b];
        g_rp[i] = r;
        g_cur[i] = r;
    }
    if (i == 0) g_rp[N_NODES] = N_EDGES;
}

__global__ void k_norm_scatter(const float* __restrict__ w) {
    int e = blockIdx.x * blockDim.x + threadIdx.x;
    if (e >= N_EDGES) return;
    int s = g_src[e], d = g_dst[e];
    float nm = g_dinv[s] * w[e] * g_dinv[d];
    int pos = atomicAdd(&g_cur[d], 1);
    if (pos < N_EDGES) {
        g_ss[pos] = s;
        g_sn[pos] = nm;
    }
}

// ---------------- CSR gather aggregation over fp16 rows (C=128) ----------------
// out[n] = (BIAS? bias:0) + dinv[n]^2*h[n] + sum_j norm[j]*h[src[j]], one warp/node.
// Lane handles 4 consecutive cols (uint2 = 4 halves = 8B -> 256B/row, coalesced).
template <bool BIAS>
__global__ void __launch_bounds__(256) k_aggh(const __half* __restrict__ h,
                                              const float* __restrict__ bias,
                                              float* __restrict__ out) {
    const int warp = (blockIdx.x * blockDim.x + threadIdx.x) >> 5;
    const int lane = threadIdx.x & 31;
    if (warp >= N_NODES) return;
    const uint2* h4 = (const uint2*)h;   // 4 halves per entry, 32 entries per row
    float di = g_dinv[warp];
    float sw = di * di;

    float4 acc;
    {
        uint2 hv = h4[(size_t)warp * 32 + lane];
        float2 f0 = __half22float2(*(const __half2*)&hv.x);
        float2 f1 = __half22float2(*(const __half2*)&hv.y);
        acc = make_float4(sw * f0.x, sw * f0.y, sw * f1.x, sw * f1.y);
        if (BIAS) {
            float4 bv = ((const float4*)bias)[lane];
            acc.x += bv.x; acc.y += bv.y; acc.z += bv.z; acc.w += bv.w;
        }
    }

    int beg = g_rp[warp], end = g_rp[warp + 1];
    int j = beg;
    for (; j + 1 < end; j += 2) {           // 2x unroll -> 2x gather MLP
        int   s0 = g_ss[j],     s1 = g_ss[j + 1];
        float n0 = g_sn[j],     n1 = g_sn[j + 1];
        uint2 t0 = h4[(size_t)s0 * 32 + lane];
        uint2 t1 = h4[(size_t)s1 * 32 + lane];
        float2 a0 = __half22float2(*(const __half2*)&t0.x);
        float2 a1 = __half22float2(*(const __half2*)&t0.y);
        float2 b0 = __half22float2(*(const __half2*)&t1.x);
        float2 b1 = __half22float2(*(const __half2*)&t1.y);
        acc.x += n0 * a0.x + n1 * b0.x;
        acc.y += n0 * a0.y + n1 * b0.y;
        acc.z += n0 * a1.x + n1 * b1.x;
        acc.w += n0 * a1.y + n1 * b1.y;
    }
    if (j < end) {
        int   s0 = g_ss[j];
        float n0 = g_sn[j];
        uint2 t0 = h4[(size_t)s0 * 32 + lane];
        float2 a0 = __half22float2(*(const __half2*)&t0.x);
        float2 a1 = __half22float2(*(const __half2*)&t0.y);
        acc.x += n0 * a0.x;
        acc.y += n0 * a0.y;
        acc.z += n0 * a1.x;
        acc.w += n0 * a1.y;
    }
    ((float4*)out)[(size_t)warp * 32 + lane] = acc;
}

// ---------------- tf32 tensor-core GEMM: C[M,Nn] = A[M,K] @ B[K,Nn] ----------------
// BM=128, BN=128, BK=8. 256 threads = 8 warps (4 m x 2 n slices, 32x64 each).
// MODE 1: C=fp32, epilogue relu(acc+bias)+JAX dropout. MODE 2: C=fp16 plain.
template <int MODE>
__global__ void __launch_bounds__(256) k_gemm_tc(const float* __restrict__ A,
                                                 const float* __restrict__ B,
                                                 const float* __restrict__ bias,
                                                 void* __restrict__ Cout,
                                                 int M, int Nn, int K) {
    __shared__ uint32_t As[128][12];   // [m][k], stride 12: conflict-free frags
    __shared__ uint32_t Bs[8][136];    // [k][n], stride 136: conflict-free frags
    const int tid  = threadIdx.x;
    const int brow = blockIdx.y * 128;
    const int bcol = blockIdx.x * 128;
    const int warp = tid >> 5, lane = tid & 31;
    const int wm = warp & 3, wn = warp >> 2;
    const int g  = lane >> 2, tg = lane & 3;

    float acc[2][8][4];
#pragma unroll
    for (int mt = 0; mt < 2; mt++)
#pragma unroll
        for (int nt = 0; nt < 8; nt++)
#pragma unroll
            for (int r = 0; r < 4; r++) acc[mt][nt][r] = 0.0f;

    const int arow = tid >> 1;
    const int acol = (tid & 1) * 4;
    const int bk   = tid >> 5;
    const int bcl  = (tid & 31) * 4;
    const int ar_g = brow + arow;
    const bool a_ok = ar_g < M;

    float4 av = make_float4(0.f, 0.f, 0.f, 0.f);
    if (a_ok) av = *(const float4*)&A[(size_t)ar_g * K + acol];
    float4 bv = *(const float4*)&B[(size_t)bk * Nn + bcol + bcl];

    const int n_iter = K >> 3;
    for (int it = 0; it < n_iter; it++) {
        uint4 at = make_uint4(f2tf32(av.x), f2tf32(av.y), f2tf32(av.z), f2tf32(av.w));
        uint4 bt = make_uint4(f2tf32(bv.x), f2tf32(bv.y), f2tf32(bv.z), f2tf32(bv.w));
        *(uint4*)&As[arow][acol] = at;
        *(uint4*)&Bs[bk][bcl]    = bt;
        __syncthreads();
        if (it + 1 < n_iter) {
            int k0 = (it + 1) << 3;
            av = make_float4(0.f, 0.f, 0.f, 0.f);
            if (a_ok) av = *(const float4*)&A[(size_t)ar_g * K + k0 + acol];
            bv = *(const float4*)&B[(size_t)(k0 + bk) * Nn + bcol + bcl];
        }
        uint32_t af[2][4];
#pragma unroll
        for (int mt = 0; mt < 2; mt++) {
            int rb = wm * 32 + mt * 16;
            af[mt][0] = As[rb + g][tg];
            af[mt][1] = As[rb + g + 8][tg];
            af[mt][2] = As[rb + g][tg + 4];
            af[mt][3] = As[rb + g + 8][tg + 4];
        }
#pragma unroll
        for (int nt = 0; nt < 8; nt++) {
            int cb = wn * 64 + nt * 8 + g;
            uint32_t b0 = Bs[tg][cb];
            uint32_t b1 = Bs[tg + 4][cb];
#pragma unroll
            for (int mt = 0; mt < 2; mt++) {
                asm volatile(
                    "mma.sync.aligned.m16n8k8.row.col.f32.tf32.tf32.f32 "
                    "{%0,%1,%2,%3}, {%4,%5,%6,%7}, {%8,%9}, {%0,%1,%2,%3};\n"
                    : "+f"(acc[mt][nt][0]), "+f"(acc[mt][nt][1]),
                      "+f"(acc[mt][nt][2]), "+f"(acc[mt][nt][3])
                    : "r"(af[mt][0]), "r"(af[mt][1]), "r"(af[mt][2]), "r"(af[mt][3]),
                      "r"(b0), "r"(b1));
            }
        }
        __syncthreads();
    }

#pragma unroll
    for (int mt = 0; mt < 2; mt++) {
#pragma unroll
        for (int half = 0; half < 2; half++) {
            int row = brow + wm * 32 + mt * 16 + g + half * 8;
            if (row >= M) continue;
#pragma unroll
            for (int nt = 0; nt < 8; nt++) {
                int col = bcol + wn * 64 + nt * 8 + tg * 2;
                float v0 = acc[mt][nt][half * 2 + 0];
                float v1 = acc[mt][nt][half * 2 + 1];
                if (MODE == 1) {
                    v0 = fmaxf(v0 + __ldg(&bias[col]), 0.0f);
                    v1 = fmaxf(v1 + __ldg(&bias[col + 1]), 0.0f);
                    uint32_t i0 = (uint32_t)row * 256u + (uint32_t)col;
                    v0 = drop_keep(i0)      ? 2.0f * v0 : 0.0f;
                    v1 = drop_keep(i0 + 1u) ? 2.0f * v1 : 0.0f;
                    *(float2*)&((float*)Cout)[(size_t)row * Nn + col] = make_float2(v0, v1);
                } else {
                    __half2 hv = __floats2half2_rn(v0, v1);
                    *(__half2*)&((__half*)Cout)[(size_t)row * Nn + col] = hv;
                }
            }
        }
    }
}

// ---------------- launch ----------------
extern "C" void kernel_launch(void* const* d_in, const int* in_sizes, int n_in,
                              void* d_out, int out_size) {
    // Identify inputs by element count (robust to metadata ordering)
    const float* x = nullptr; const void* ei = nullptr; const float* w = nullptr;
    const float* W1 = nullptr; const float* b1 = nullptr;
    const float* W2 = nullptr; const float* b2 = nullptr;
    for (int i = 0; i < n_in; i++) {
        int sz = in_sizes[i];
        const void* p = d_in[i];
        switch (sz) {
            case 6400000: x  = (const float*)p; break;
            case 1600000: ei = p; break;
            case 800000:  w  = (const float*)p; break;
            case 32768:   if (!W1) W1 = (const float*)p; else W2 = (const float*)p; break;
            case 256:     b1 = (const float*)p; break;
            case 128:     b2 = (const float*)p; break;
            default: break;
        }
    }
    float* out = (float*)d_out;

    __half* xh;  cudaGetSymbolAddress((void**)&xh,  g_xh);
    float*  ax;  cudaGetSymbolAddress((void**)&ax,  g_ax);
    float*  h1d; cudaGetSymbolAddress((void**)&h1d, g_h1d);
    __half* h2h; cudaGetSymbolAddress((void**)&h2h, g_h2h);

    const int TB = 256;
    // prep: init(+detect), x->fp16, edges, scans(+dinv), norm scatter
    k_init<<<(N_NODES + TB - 1) / TB, TB>>>((const unsigned*)ei);
    k_cvt_x<<<(N_NODES * (C_OUT / 4) + TB - 1) / TB, TB>>>(x);
    k_prep_edges<<<(N_EDGES + TB - 1) / TB, TB>>>(ei, w);
    k_scan1<<<NB, SCAN_B>>>();
    k_scan2<<<1, 128>>>();
    k_scan3<<<NB, SCAN_B>>>();
    k_norm_scatter<<<(N_EDGES + TB - 1) / TB, TB>>>(w);

    // Layer 1 (reordered): ax = A_hat @ x ; h1d = dropout(relu(ax@W1 + b1))
    k_aggh<false><<<(N_NODES * 32 + TB - 1) / TB, TB>>>(xh, nullptr, ax);
    k_gemm_tc<1><<<dim3(C_HID / 128, (N_NODES + 127) / 128), 256>>>(
        ax, W1, b1, h1d, N_NODES, C_HID, 128);

    // Layer 2: h2h = h1d @ W2 (fp16) ; out = A_hat @ h2h + b2
    k_gemm_tc<2><<<dim3(C_OUT / 128, (N_NODES + 127) / 128), 256>>>(
        h1d, W2, nullptr, h2h, N_NODES, C_OUT, C_HID);
    k_aggh<true><<<(N_NODES * 32 + TB - 1) / TB, TB>>>(h2h, b2, out);
}

// round 10
// speedup vs baseline: 1.7988x; 1.0091x over previous
#include <cuda_runtime.h>
#include <cuda_fp16.h>
#include <cstdint>
#include <cstddef>

#define N_NODES 50000
#define N_PAD   50048                      // padded row count (multiple of 128)
#define N_EDGES 800000
#define C_HID   256
#define C_OUT   128
#define SCAN_B  512
#define NB      ((N_NODES + SCAN_B - 1) / SCAN_B)   // 98
#define N_MASKB (N_NODES * C_HID / 8)      // 1,600,000 bytes of dropout mask

// ---------------- scratch (static device globals; no allocation) ----------------
__device__ __align__(16) float    g_deg [N_NODES];
__device__ __align__(16) float    g_dinv[N_NODES];
__device__ __align__(16) int      g_src [N_EDGES];
__device__ __align__(16) int      g_dst [N_EDGES];
__device__ __align__(16) int      g_cnt [N_NODES];
__device__ __align__(16) int      g_rp  [N_NODES];     // block-local exclusive scan
__device__ __align__(16) int      g_cur [N_NODES];     // running copy of g_rp
__device__ __align__(16) int      g_bsum[NB];
__device__ __align__(16) int      g_boff[NB];          // block offsets (scan of bsum)
__device__ __align__(16) int      g_ss  [N_EDGES];     // CSR: src sorted by dst
__device__ __align__(16) float    g_sn  [N_EDGES];     // CSR: norm sorted by dst
__device__ __align__(16) uint8_t  g_mask8[N_MASKB];    // JAX dropout keep-bits
__device__ __align__(16) __half   g_xh  [(size_t)N_NODES * C_OUT];   // x in fp16
__device__ __align__(16) float    g_ax  [(size_t)N_PAD * C_OUT];     // A_hat @ x
__device__ __align__(16) float    g_h1d [(size_t)N_PAD * C_HID];     // layer-1 act
__device__ __align__(16) __half   g_h2h [(size_t)N_PAD * C_OUT];     // h1d @ W2 fp16
__device__ int g_mode;      // 0=int64, 1=int32, 2=float32 storage of edge_index

// ---------------- threefry-2x32 (JAX partitionable convention) ----------------
__device__ __forceinline__ uint32_t rotl32(uint32_t x, int d) {
    return (x << d) | (x >> (32 - d));
}
__device__ __forceinline__ void threefry2x32(uint32_t k0, uint32_t k1,
                                             uint32_t& x0, uint32_t& x1) {
    uint32_t ks0 = k0, ks1 = k1, ks2 = k0 ^ k1 ^ 0x1BD11BDAu;
    x0 += ks0; x1 += ks1;
#define TF_GROUP(a,b,c,d) \
    x0 += x1; x1 = rotl32(x1,a); x1 ^= x0; \
    x0 += x1; x1 = rotl32(x1,b); x1 ^= x0; \
    x0 += x1; x1 = rotl32(x1,c); x1 ^= x0; \
    x0 += x1; x1 = rotl32(x1,d); x1 ^= x0;
    TF_GROUP(13,15,26,6)   x0 += ks1; x1 += ks2 + 1u;
    TF_GROUP(17,29,16,24)  x0 += ks2; x1 += ks0 + 2u;
    TF_GROUP(13,15,26,6)   x0 += ks0; x1 += ks1 + 3u;
    TF_GROUP(17,29,16,24)  x0 += ks1; x1 += ks2 + 4u;
    TF_GROUP(13,15,26,6)   x0 += ks2; x1 += ks0 + 5u;
#undef TF_GROUP
}
// keep ⟺ u<0.5 ⟺ top bit of (y0^y1) clear
__device__ __forceinline__ uint32_t drop_keep_bit(uint32_t i) {
    uint32_t x0 = 0u, x1 = i;
    threefry2x32(0u, 42u, x0, x1);
    return ((x0 ^ x1) >> 31) ^ 1u;
}

__device__ __forceinline__ uint32_t f2tf32(float f) {
    uint32_t r;
    asm("cvt.rna.tf32.f32 %0, %1;" : "=r"(r) : "f"(f));
    return r;
}

// ---------------- x -> fp16, + deg/cnt init, + dtype detect ----------------
__global__ void k_cvt_x(const float* __restrict__ x, const unsigned* __restrict__ eiw) {
    int i = blockIdx.x * blockDim.x + threadIdx.x;     // float4 index, 1.6M total
    if (i < N_NODES) { g_deg[i] = 1.0f; g_cnt[i] = 0; }
    if (blockIdx.x == 0) {
        __shared__ int s_odd, s_big;
        int t = threadIdx.x;
        if (t == 0) { s_odd = 0; s_big = 0; }
        __syncthreads();
        unsigned v0 = eiw[2 * t];
        unsigned v1 = eiw[2 * t + 1];
        if (v0 >= 0x30000000u || v1 >= 0x30000000u) atomicOr(&s_big, 1);
        if (v1 != 0u) atomicOr(&s_odd, 1);
        __syncthreads();
        if (t == 0) g_mode = s_big ? 2 : (s_odd ? 1 : 0);
    }
    if (i >= N_NODES * (C_OUT / 4)) return;
    float4 v = ((const float4*)x)[i];
    __half2 a = __floats2half2_rn(v.x, v.y);
    __half2 b = __floats2half2_rn(v.z, v.w);
    ((uint2*)g_xh)[i] = make_uint2(*(uint32_t*)&a, *(uint32_t*)&b);
}

__global__ void k_prep_edges(const void* __restrict__ ei_raw,
                             const float* __restrict__ w) {
    int e = blockIdx.x * blockDim.x + threadIdx.x;
    if (e >= N_EDGES) return;
    int s, d;
    int mode = g_mode;
    if (mode == 2) {
        const float* ei = (const float*)ei_raw;
        s = (int)ei[e];
        d = (int)ei[N_EDGES + e];
    } else if (mode == 1) {
        const int* ei = (const int*)ei_raw;
        s = ei[e];
        d = ei[N_EDGES + e];
    } else {
        const long long* ei = (const long long*)ei_raw;
        s = (int)ei[e];
        d = (int)ei[N_EDGES + e];
    }
    s = min(max(s, 0), N_NODES - 1);
    d = min(max(d, 0), N_NODES - 1);
    g_src[e] = s; g_dst[e] = d;
    atomicAdd(&g_deg[d], w[e]);
    atomicAdd(&g_cnt[d], 1);
}

// ---------------- scan1: block-local exclusive scan of cnt (+dinv, +cur) ----------------
__global__ void __launch_bounds__(SCAN_B) k_scan1() {
    __shared__ int ws[16];
    int b = blockIdx.x, t = threadIdx.x;
    int i = b * SCAN_B + t;
    int lane = t & 31, wid = t >> 5;
    int v = (i < N_NODES) ? g_cnt[i] : 0;
    if (i < N_NODES) g_dinv[i] = rsqrtf(g_deg[i]);   // deg >= 1 always
    int x = v;
#pragma unroll
    for (int o = 1; o < 32; o <<= 1) {
        int y = __shfl_up_sync(~0u, x, o);
        if (lane >= o) x += y;
    }
    if (lane == 31) ws[wid] = x;
    __syncthreads();
    if (wid == 0) {
        int s = (lane < 16) ? ws[lane] : 0;
#pragma unroll
        for (int o = 1; o < 16; o <<= 1) {
            int y = __shfl_up_sync(~0u, s, o);
            if (lane >= o) s += y;
        }
        if (lane < 16) ws[lane] = s;
    }
    __syncthreads();
    int excl = x - v + (wid > 0 ? ws[wid - 1] : 0);
    if (i < N_NODES) {
        g_rp[i]  = excl;      // block-local; final = + g_boff[b]
        g_cur[i] = excl;
    }
    if (t == 0) g_bsum[b] = ws[15];
}

__global__ void k_scan2() {
    __shared__ int ws[4];
    int t = threadIdx.x;
    int lane = t & 31, wid = t >> 5;
    int v = (t < NB) ? g_bsum[t] : 0;
    int x = v;
#pragma unroll
    for (int o = 1; o < 32; o <<= 1) {
        int y = __shfl_up_sync(~0u, x, o);
        if (lane >= o) x += y;
    }
    if (lane == 31) ws[wid] = x;
    __syncthreads();
    if (wid == 0 && lane < 4) {
        int s = ws[lane];
#pragma unroll
        for (int o = 1; o < 4; o <<= 1) {
            int y = __shfl_up_sync(0xFu, s, o);
            if (lane >= o) s += y;
        }
        ws[lane] = s;
    }
    __syncthreads();
    int excl = x - v + (wid > 0 ? ws[wid - 1] : 0);
    if (t < NB) g_boff[t] = excl;
}

// norm + scatter into CSR order (final position = local cur + block offset)
__global__ void k_norm_scatter(const float* __restrict__ w) {
    int e = blockIdx.x * blockDim.x + threadIdx.x;
    if (e >= N_EDGES) return;
    int s = g_src[e], d = g_dst[e];
    float nm = g_dinv[s] * w[e] * g_dinv[d];
    int pos = atomicAdd(&g_cur[d], 1) + g_boff[d >> 9];
    if ((unsigned)pos < N_EDGES) {
        g_ss[pos] = s;
        g_sn[pos] = nm;
    }
}

// CSR row bounds with lazily-applied block offsets
__device__ __forceinline__ int rp_final(int n) {
    return (n >= N_NODES) ? N_EDGES : (g_rp[n] + g_boff[n >> 9]);
}

// ---------------- CSR gather aggregation over fp16 rows (C=128) ----------------
// out[n] = (BIAS? bias:0) + dinv[n]^2*h[n] + sum_j norm[j]*h[src[j]], one warp/node.
// MASK: additionally each thread computes 8 JAX dropout keep-bits (ALU work hidden
// under the gather latency) -> g_mask8. Grid is exactly N_NODES*32 threads.
template <bool BIAS, bool MASK>
__global__ void __launch_bounds__(256) k_aggh(const __half* __restrict__ h,
                                              const float* __restrict__ bias,
                                              float* __restrict__ out) {
    const int gtid = blockIdx.x * blockDim.x + threadIdx.x;
    const int warp = gtid >> 5;
    const int lane = threadIdx.x & 31;
    if (warp >= N_NODES) return;
    const uint2* h4 = (const uint2*)h;
    float di = g_dinv[warp];
    float sw = di * di;

    int beg = rp_final(warp), end = rp_final(warp + 1);

    float4 acc;
    {
        uint2 hv = h4[(size_t)warp * 32 + lane];
        float2 f0 = __half22float2(*(const __half2*)&hv.x);
        float2 f1 = __half22float2(*(const __half2*)&hv.y);
        acc = make_float4(sw * f0.x, sw * f0.y, sw * f1.x, sw * f1.y);
        if (BIAS) {
            float4 bv = ((const float4*)bias)[lane];
            acc.x += bv.x; acc.y += bv.y; acc.z += bv.z; acc.w += bv.w;
        }
    }

    if (MASK) {   // 8 threefry hashes per thread; overlaps with gathers below
        uint32_t base = (uint32_t)gtid * 8u;
        uint32_t m = 0;
#pragma unroll
        for (int b = 0; b < 8; b++) m |= drop_keep_bit(base + b) << b;
        g_mask8[gtid] = (uint8_t)m;
    }

    int j = beg;
    for (; j + 3 < end; j += 4) {           // 4-way MLP on the latency-bound path
        int   s0 = g_ss[j],   s1 = g_ss[j+1], s2 = g_ss[j+2], s3 = g_ss[j+3];
        float n0 = g_sn[j],   n1 = g_sn[j+1], n2 = g_sn[j+2], n3 = g_sn[j+3];
        uint2 t0 = h4[(size_t)s0 * 32 + lane];
        uint2 t1 = h4[(size_t)s1 * 32 + lane];
        uint2 t2 = h4[(size_t)s2 * 32 + lane];
        uint2 t3 = h4[(size_t)s3 * 32 + lane];
        float2 a0 = __half22float2(*(const __half2*)&t0.x);
        float2 a1 = __half22float2(*(const __half2*)&t0.y);
        float2 b0 = __half22float2(*(const __half2*)&t1.x);
        float2 b1 = __half22float2(*(const __half2*)&t1.y);
        float2 c0 = __half22float2(*(const __half2*)&t2.x);
        float2 c1 = __half22float2(*(const __half2*)&t2.y);
        float2 d0 = __half22float2(*(const __half2*)&t3.x);
        float2 d1 = __half22float2(*(const __half2*)&t3.y);
        acc.x += n0 * a0.x + n1 * b0.x + n2 * c0.x + n3 * d0.x;
        acc.y += n0 * a0.y + n1 * b0.y + n2 * c0.y + n3 * d0.y;
        acc.z += n0 * a1.x + n1 * b1.x + n2 * c1.x + n3 * d1.x;
        acc.w += n0 * a1.y + n1 * b1.y + n2 * c1.y + n3 * d1.y;
    }
    for (; j < end; j++) {
        int   s0 = g_ss[j];
        float n0 = g_sn[j];
        uint2 t0 = h4[(size_t)s0 * 32 + lane];
        float2 a0 = __half22float2(*(const __half2*)&t0.x);
        float2 a1 = __half22float2(*(const __half2*)&t0.y);
        acc.x += n0 * a0.x;
        acc.y += n0 * a0.y;
        acc.z += n0 * a1.x;
        acc.w += n0 * a1.y;
    }
    ((float4*)out)[(size_t)warp * 32 + lane] = acc;
}

// ---------------- tf32 tensor-core GEMM: C[M,Nn] = A[M,K] @ B[K,Nn] ----------------
// BM=128, BN=128, BK=8. 256 threads = 8 warps (4 m x 2 n slices, 32x64 each).
// MODE 1: C=fp32, epilogue relu(acc+bias) * precomputed dropout mask * 2.
// MODE 2: C=fp16 plain.
template <int MODE>
__global__ void __launch_bounds__(256) k_gemm_tc(const float* __restrict__ A,
                                                 const float* __restrict__ B,
                                                 const float* __restrict__ bias,
                                                 void* __restrict__ Cout,
                                                 int M, int Nn, int K) {
    __shared__ uint32_t As[128][12];   // [m][k], stride 12: conflict-free frags
    __shared__ uint32_t Bs[8][136];    // [k][n], stride 136: conflict-free frags
    const int tid  = threadIdx.x;
    const int brow = blockIdx.y * 128;
    const int bcol = blockIdx.x * 128;
    const int warp = tid >> 5, lane = tid & 31;
    const int wm = warp & 3, wn = warp >> 2;
    const int g  = lane >> 2, tg = lane & 3;

    float acc[2][8][4];
#pragma unroll
    for (int mt = 0; mt < 2; mt++)
#pragma unroll
        for (int nt = 0; nt < 8; nt++)
#pragma unroll
            for (int r = 0; r < 4; r++) acc[mt][nt][r] = 0.0f;

    const int arow = tid >> 1;
    const int acol = (tid & 1) * 4;
    const int bk   = tid >> 5;
    const int bcl  = (tid & 31) * 4;
    const int ar_g = brow + arow;
    const bool a_ok = ar_g < M;

    float4 av = make_float4(0.f, 0.f, 0.f, 0.f);
    if (a_ok) av = *(const float4*)&A[(size_t)ar_g * K + acol];
    float4 bv = *(const float4*)&B[(size_t)bk * Nn + bcol + bcl];

    const int n_iter = K >> 3;
    for (int it = 0; it < n_iter; it++) {
        uint4 at = make_uint4(f2tf32(av.x), f2tf32(av.y), f2tf32(av.z), f2tf32(av.w));
        uint4 bt = make_uint4(f2tf32(bv.x), f2tf32(bv.y), f2tf32(bv.z), f2tf32(bv.w));
        *(uint4*)&As[arow][acol] = at;
        *(uint4*)&Bs[bk][bcl]    = bt;
        __syncthreads();
        if (it + 1 < n_iter) {
            int k0 = (it + 1) << 3;
            av = make_float4(0.f, 0.f, 0.f, 0.f);
            if (a_ok) av = *(const float4*)&A[(size_t)ar_g * K + k0 + acol];
            bv = *(const float4*)&B[(size_t)(k0 + bk) * Nn + bcol + bcl];
        }
        uint32_t af[2][4];
#pragma unroll
        for (int mt = 0; mt < 2; mt++) {
            int rb = wm * 32 + mt * 16;
            af[mt][0] = As[rb + g][tg];
            af[mt][1] = As[rb + g + 8][tg];
            af[mt][2] = As[rb + g][tg + 4];
            af[mt][3] = As[rb + g + 8][tg + 4];
        }
#pragma unroll
        for (int nt = 0; nt < 8; nt++) {
            int cb = wn * 64 + nt * 8 + g;
            uint32_t b0 = Bs[tg][cb];
            uint32_t b1 = Bs[tg + 4][cb];
#pragma unroll
            for (int mt = 0; mt < 2; mt++) {
                asm volatile(
                    "mma.sync.aligned.m16n8k8.row.col.f32.tf32.tf32.f32 "
                    "{%0,%1,%2,%3}, {%4,%5,%6,%7}, {%8,%9}, {%0,%1,%2,%3};\n"
                    : "+f"(acc[mt][nt][0]), "+f"(acc[mt][nt][1]),
                      "+f"(acc[mt][nt][2]), "+f"(acc[mt][nt][3])
                    : "r"(af[mt][0]), "r"(af[mt][1]), "r"(af[mt][2]), "r"(af[mt][3]),
                      "r"(b0), "r"(b1));
            }
        }
        __syncthreads();
    }

    const uint32_t* maskw = (const uint32_t*)g_mask8;   // 8 words per row (256 bits)
#pragma unroll
    for (int mt = 0; mt < 2; mt++) {
#pragma unroll
        for (int half = 0; half < 2; half++) {
            int row = brow + wm * 32 + mt * 16 + g + half * 8;
            if (row >= M) continue;
            uint32_t w0 = 0, w1 = 0;
            if (MODE == 1) {
                // word index includes bcol: columns [bcol+wn*64, bcol+wn*64+64)
                int wbase = row * 8 + ((bcol + wn * 64) >> 5);
                w0 = maskw[wbase + 0];
                w1 = maskw[wbase + 1];
            }
#pragma unroll
            for (int nt = 0; nt < 8; nt++) {
                int coff = nt * 8 + tg * 2;               // 0..62 within 64-col slice
                int col  = bcol + wn * 64 + coff;
                float v0 = acc[mt][nt][half * 2 + 0];
                float v1 = acc[mt][nt][half * 2 + 1];
                if (MODE == 1) {
                    v0 = fmaxf(v0 + __ldg(&bias[col]), 0.0f);
                    v1 = fmaxf(v1 + __ldg(&bias[col + 1]), 0.0f);
                    uint32_t w = (coff < 32) ? w0 : w1;
                    int bit = coff & 31;
                    v0 = (w >> bit & 1u)       ? 2.0f * v0 : 0.0f;
                    v1 = (w >> (bit + 1) & 1u) ? 2.0f * v1 : 0.0f;
                    *(float2*)&((float*)Cout)[(size_t)row * Nn + col] = make_float2(v0, v1);
                } else {
                    __half2 hv = __floats2half2_rn(v0, v1);
                    *(__half2*)&((__half*)Cout)[(size_t)row * Nn + col] = hv;
                }
            }
        }
    }
}

// ---------------- launch ----------------
extern "C" void kernel_launch(void* const* d_in, const int* in_sizes, int n_in,
                              void* d_out, int out_size) {
    // Identify inputs by element count (robust to metadata ordering)
    const float* x = nullptr; const void* ei = nullptr; const float* w = nullptr;
    const float* W1 = nullptr; const float* b1 = nullptr;
    const float* W2 = nullptr; const float* b2 = nullptr;
    for (int i = 0; i < n_in; i++) {
        int sz = in_sizes[i];
        const void* p = d_in[i];
        switch (sz) {
            case 6400000: x  = (const float*)p; break;
            case 1600000: ei = p; break;
            case 800000:  w  = (const float*)p; break;
            case 32768:   if (!W1) W1 = (const float*)p; else W2 = (const float*)p; break;
            case 256:     b1 = (const float*)p; break;
            case 128:     b2 = (const float*)p; break;
            default: break;
        }
    }
    float* out = (float*)d_out;

    __half* xh;  cudaGetSymbolAddress((void**)&xh,  g_xh);
    float*  ax;  cudaGetSymbolAddress((void**)&ax,  g_ax);
    float*  h1d; cudaGetSymbolAddress((void**)&h1d, g_h1d);
    __half* h2h; cudaGetSymbolAddress((void**)&h2h, g_h2h);

    const int TB = 256;
    // prep: cvt(+init+detect), edges, scan1(+dinv), scan2, norm_scatter(+boff)
    k_cvt_x<<<(N_NODES * (C_OUT / 4) + TB - 1) / TB, TB>>>(x, (const unsigned*)ei);
    k_prep_edges<<<(N_EDGES + TB - 1) / TB, TB>>>(ei, w);
    k_scan1<<<NB, SCAN_B>>>();
    k_scan2<<<1, 128>>>();
    k_norm_scatter<<<(N_EDGES + TB - 1) / TB, TB>>>(w);

    // Layer 1 (reordered): ax = A_hat @ x (+dropout mask gen) ; h1d = drop(relu(axW1+b1))
    k_aggh<false, true><<<N_NODES * 32 / TB, TB>>>(xh, nullptr, ax);
    k_gemm_tc<1><<<dim3(C_HID / 128, (N_NODES + 127) / 128), 256>>>(
        ax, W1, b1, h1d, N_NODES, C_HID, 128);

    // Layer 2: h2h = h1d @ W2 (fp16) ; out = A_hat @ h2h + b2
    k_gemm_tc<2><<<dim3(C_OUT / 128, (N_NODES + 127) / 128), 256>>>(
        h1d, W2, nullptr, h2h, N_NODES, C_OUT, C_HID);
    k_aggh<true, false><<<N_NODES * 32 / TB, TB>>>(h2h, b2, out);
}